// round 11
// baseline (speedup 1.0000x reference)
#include <cuda_runtime.h>
#include <math.h>

// z: (16, 10, 64, 64) f32.  B=16, C=10 bits, NPIX=65536, NELEM=655360.
// Output layout (f32, reference tuple order):
//   [0, 655360)        z_quantized (b,c,h,w)  = sign(z) in {-1,+1}
//   [655360]           loss
//   [655361]           per_sample_entropy
//   [655362, 720898)   min_encoding_indices (b,h,w) cast to float

#define OFF_LOSS  655360
#define OFF_PSE   655361
#define OFF_IDX   655362

__device__ float    g_avg[1024];
__device__ float    g_commit;
__device__ float    g_ent;
__device__ unsigned g_count;

// Packed dual-FMA: d.xy += a.xy * b.xy  (sm_100+ FFMA2, PTX-only)
#define FMA2(d, a, b) \
    asm("fma.rn.f32x2 %0, %1, %2, %0;" : "+l"(d) : "l"(a), "l"(b))

// Single fused kernel. Per block: 128 pixels, 8 warps, 16 pixels per warp.
// The 1024-way softmax factorizes into 10 Bernoullis (q_c = sigmoid(400 z_c)):
//   p_n = lo[n&31] * hi[n>>5], per_sample_entropy = sum of 10 binary entropies.
// Each warp accumulates the full 32x32 outer-product sum over its pixels in
// 32 register accumulators per lane (code n = (j<<5)|lane), sync-free.
__global__ void __launch_bounds__(256) k_fused(const float* __restrict__ z,
                                               float* __restrict__ out) {
    __shared__ __align__(16) float sm[8192];   // 32 KB, overlaid regions
    __shared__ float s_red[8];
    __shared__ unsigned s_ticket;

    float (*qb)[12]      = (float(*)[12])sm;                   // [128][12]
    float (*hib)[16][32] = (float(*)[16][32])(sm + 1536);      // [8][16][32]

    int tid  = threadIdx.x;
    int lane = tid & 31;
    int w    = tid >> 5;
    int pix0 = blockIdx.x * 128;

    // ---- Load + elementwise pass (coalesced, c-major) ----
    float commit = 0.0f, H = 0.0f;
    #pragma unroll
    for (int k = 0; k < 5; k++) {
        int v = tid + k * 256;          // [0,1280)
        int c = v >> 7, p = v & 127;
        int pix = pix0 + p;
        int b = pix >> 12, hw = pix & 4095;
        int off = b * 40960 + c * 4096 + hw;
        float zv = z[off];
        bool s = (zv > 0.0f);
        float sg = s ? 1.0f : -1.0f;
        out[off] = sg;                  // z_quantized
        float d = sg - zv;
        commit += d * d;
        // binary entropy of q = sigmoid(400 zv): H2 = log(1+e) + t*e/(1+e)
        float t = 400.0f * fabsf(zv);
        float e = __expf(-t);
        float inv = 1.0f / (1.0f + e);
        H += __logf(1.0f + e) + t * e * inv;
        qb[p][c] = s ? inv : e * inv;   // sigmoid, overflow-free
    }
    #pragma unroll
    for (int o = 16; o; o >>= 1) {
        commit += __shfl_down_sync(0xffffffffu, commit, o);
        H      += __shfl_down_sync(0xffffffffu, H, o);
    }
    if (lane == 0) {
        atomicAdd(&g_commit, commit);
        atomicAdd(&g_ent, H);
    }
    __syncthreads();

    // ---- Index packing (q > 0.5  <=>  z > 0, incl. z==0 -> false) ----
    if (tid < 128) {
        int idx = 0;
        #pragma unroll
        for (int c = 0; c < 10; c++) idx |= ((int)(qb[tid][c] > 0.5f)) << c;
        out[OFF_IDX + pix0 + tid] = (float)idx;
    }

    // ---- Per-lane subset-product constants: sel = sv*q + cv ----
    float sv[5], cv[5];
    #pragma unroll
    for (int k = 0; k < 5; k++) {
        bool b = (lane >> k) & 1;
        sv[k] = b ? 1.0f : -1.0f;
        cv[k] = b ? 0.0f : 1.0f;
    }

    // ---- Phase 1: lo in registers, hi to warp-private smem ----
    float lo[16];
    #pragma unroll
    for (int p = 0; p < 16; p++) {
        int row = w * 16 + p;
        const float4* q4 = (const float4*)qb[row];
        float4 f1 = q4[0];                            // q0..q3
        float4 f2 = q4[1];                            // q4..q7
        float2 f3 = *(const float2*)(qb[row] + 8);    // q8,q9
        float L = fmaf(sv[0], f1.x, cv[0]);
        L *= fmaf(sv[1], f1.y, cv[1]);
        L *= fmaf(sv[2], f1.z, cv[2]);
        L *= fmaf(sv[3], f1.w, cv[3]);
        L *= fmaf(sv[4], f2.x, cv[4]);
        float Hi = fmaf(sv[0], f2.y, cv[0]);
        Hi *= fmaf(sv[1], f2.z, cv[1]);
        Hi *= fmaf(sv[2], f2.w, cv[2]);
        Hi *= fmaf(sv[3], f3.x, cv[3]);
        Hi *= fmaf(sv[4], f3.y, cv[4]);
        lo[p] = L;
        hib[w][p][lane] = Hi;
    }
    __syncwarp();

    // ---- Phase 2: 32x32 outer-product accumulation, FFMA2, sync-free ----
    unsigned long long acc[16];
    #pragma unroll
    for (int a = 0; a < 16; a++) acc[a] = 0ull;   // (0.f, 0.f)

    #pragma unroll
    for (int p = 0; p < 16; p++) {
        unsigned r = __float_as_uint(lo[p]);
        unsigned long long lo2;
        asm("mov.b64 %0, {%1, %1};" : "=l"(lo2) : "r"(r));
        const ulonglong2* hp = (const ulonglong2*)hib[w][p];
        #pragma unroll
        for (int t = 0; t < 8; t++) {
            ulonglong2 h = hp[t];                  // broadcast LDS.128
            FMA2(acc[2 * t],     lo2, h.x);        // hi-idx 4t, 4t+1
            FMA2(acc[2 * t + 1], lo2, h.y);        // hi-idx 4t+2, 4t+3
        }
    }

    // ---- Block reduction: overlay s_acc on qb/hib, then 1024 atomics ----
    __syncthreads();                                // all reads of qb/hib done
    float (*s_acc)[32][32] = (float(*)[32][32])sm;  // [8][32][32]
    #pragma unroll
    for (int a = 0; a < 16; a++) {
        unsigned x, y;
        asm("mov.b64 {%0, %1}, %2;" : "=r"(x), "=r"(y) : "l"(acc[a]));
        s_acc[w][2 * a][lane]     = __uint_as_float(x);
        s_acc[w][2 * a + 1][lane] = __uint_as_float(y);
    }
    __syncthreads();
    #pragma unroll
    for (int k = 0; k < 4; k++) {
        int n = tid + k * 256;                      // n = (j<<5)|lane
        float s = 0.0f;
        #pragma unroll
        for (int ww = 0; ww < 8; ww++) s += sm[ww * 1024 + n];
        atomicAdd(&g_avg[n], s);
    }

    // ---- Last-block finalization (ticket) ----
    __threadfence();
    __syncthreads();
    if (tid == 0) s_ticket = atomicAdd(&g_count, 1u);
    __syncthreads();

    if (s_ticket == gridDim.x - 1) {                // uniform per block
        __threadfence();
        float ssum = 0.0f;
        #pragma unroll
        for (int k = 0; k < 4; k++) {
            float ap = g_avg[tid + 256 * k] * (1.0f / 65536.0f);
            ssum += -ap * logf(ap + 1e-5f);
            g_avg[tid + 256 * k] = 0.0f;            // reset for next replay
        }
        #pragma unroll
        for (int o = 16; o; o >>= 1) ssum += __shfl_down_sync(0xffffffffu, ssum, o);
        if (lane == 0) s_red[w] = ssum;
        __syncthreads();
        if (tid < 32) {
            float v = (tid < 8) ? s_red[tid] : 0.0f;
            #pragma unroll
            for (int o = 4; o; o >>= 1) v += __shfl_down_sync(0xffffffffu, v, o);
            if (tid == 0) {
                float avg_entropy = v;                             // gamma = 1.0
                float pse = g_ent * (1.0f / 65536.0f);
                float cm  = 0.25f * g_commit * (1.0f / 655360.0f);
                out[OFF_LOSS] = cm + 0.1f * (pse - avg_entropy);
                out[OFF_PSE]  = pse;
                g_commit = 0.0f; g_ent = 0.0f; g_count = 0u;       // reset
            }
        }
    }
}

extern "C" void kernel_launch(void* const* d_in, const int* in_sizes, int n_in,
                              void* d_out, int out_size) {
    const float* z = (const float*)d_in[0];
    float* out = (float*)d_out;
    (void)in_sizes; (void)n_in; (void)out_size;
    k_fused<<<512, 256>>>(z, out);
}

// round 12
// speedup vs baseline: 1.0660x; 1.0660x over previous
#include <cuda_runtime.h>
#include <math.h>

// z: (16, 10, 64, 64) f32.  B=16, C=10 bits, NPIX=65536, NELEM=655360.
// Output layout (f32, reference tuple order):
//   [0, 655360)        z_quantized (b,c,h,w)  = sign(z) in {-1,+1}
//   [655360]           loss
//   [655361]           per_sample_entropy
//   [655362, 720898)   min_encoding_indices (b,h,w) cast to float

#define OFF_LOSS  655360
#define OFF_PSE   655361
#define OFF_IDX   655362
#define NBANK     8

__device__ float    g_avg[NBANK][1024];
__device__ float    g_commit;
__device__ float    g_ent;
__device__ unsigned g_count;

// Packed dual-FMA: d.xy += a.xy * b.xy  (sm_100+ FFMA2, PTX-only)
#define FMA2(d, a, b) \
    asm("fma.rn.f32x2 %0, %1, %2, %0;" : "+l"(d) : "l"(a), "l"(b))

// One fused kernel, 1024 blocks x 64 pixels. The 1024-way softmax factorizes
// into 10 Bernoullis (q_c = sigmoid(400 z_c)):
//   p_n = lo[n&31] * hi[n>>5];  per_sample_entropy = sum of binary entropies.
// Mainloop: 4 stages of 16 pixels. Phase B: even warps build lo[16][32], odd
// warps build hi (permuted for float4 reads). Phase C: each thread owns codes
// n = tid + 256k, accumulated as two packed f32x2 registers.
__global__ void __launch_bounds__(256) k_fused(const float* __restrict__ z,
                                               float* __restrict__ out) {
    __shared__ float qb[64][10];
    __shared__ float lo[16][32];
    __shared__ __align__(16) float hiT[16][32];
    __shared__ float s_c[8], s_h[8], s_red[8];
    __shared__ unsigned s_ticket;

    int tid  = threadIdx.x;
    int lane = tid & 31;
    int w    = tid >> 5;
    int pix0 = blockIdx.x * 64;

    // ---- Load + elementwise pass (coalesced, c-major; 640 elems/block) ----
    float commit = 0.0f, H = 0.0f;
    #pragma unroll
    for (int k = 0; k < 3; k++) {
        int v = tid + k * 256;
        if (v < 640) {
            int c = v >> 6, p = v & 63;
            int pix = pix0 + p;
            int b = pix >> 12, hw = pix & 4095;
            int off = b * 40960 + c * 4096 + hw;
            float zv = z[off];
            bool s = (zv > 0.0f);
            float sg = s ? 1.0f : -1.0f;
            out[off] = sg;                  // z_quantized
            float d = sg - zv;
            commit += d * d;
            // binary entropy of q = sigmoid(400 zv): H2 = log(1+e) + t*e/(1+e)
            float t = 400.0f * fabsf(zv);
            float e = __expf(-t);
            float inv = 1.0f / (1.0f + e);
            H += __logf(1.0f + e) + t * e * inv;
            qb[p][c] = s ? inv : e * inv;   // sigmoid, overflow-free
        }
    }
    #pragma unroll
    for (int o = 16; o; o >>= 1) {
        commit += __shfl_down_sync(0xffffffffu, commit, o);
        H      += __shfl_down_sync(0xffffffffu, H, o);
    }
    if (lane == 0) { s_c[w] = commit; s_h[w] = H; }
    __syncthreads();

    if (tid == 0) {                         // one pair of atomics per block
        float sc = 0.0f, sh = 0.0f;
        #pragma unroll
        for (int i = 0; i < 8; i++) { sc += s_c[i]; sh += s_h[i]; }
        atomicAdd(&g_commit, sc);
        atomicAdd(&g_ent, sh);
    }

    // ---- Index packing (q > 0.5  <=>  z > 0, incl. z==0 -> false) ----
    if (tid < 64) {
        int idx = 0;
        #pragma unroll
        for (int c = 0; c < 10; c++) idx |= ((int)(qb[tid][c] > 0.5f)) << c;
        out[OFF_IDX + pix0 + tid] = (float)idx;
    }

    // ---- Per-lane subset constants: term_k = sv[k]*q + cv[k] ----
    // Thread's subset index i = lane, half = w&1 (fixed), pixel = tid>>6 + 4j.
    float sv[5], cv[5];
    #pragma unroll
    for (int k = 0; k < 5; k++) {
        bool b = (lane >> k) & 1;
        sv[k] = b ? 1.0f : -1.0f;
        cv[k] = b ? 0.0f : 1.0f;
    }
    int c0 = (w & 1) * 5;
    int plbase = tid >> 6;                  // 0..3

    unsigned long long a01 = 0ull, a23 = 0ull;   // packed f32x2 accumulators

    for (int s = 0; s < 4; s++) {           // 4 stages x 16 pixels
        // Phase B: product of 5 Bernoulli terms; broadcast qb reads.
        #pragma unroll
        for (int j = 0; j < 4; j++) {
            int pl = plbase + 4 * j;
            const float* q = qb[s * 16 + pl];
            float prod = fmaf(sv[0], q[c0 + 0], cv[0]);
            prod *= fmaf(sv[1], q[c0 + 1], cv[1]);
            prod *= fmaf(sv[2], q[c0 + 2], cv[2]);
            prod *= fmaf(sv[3], q[c0 + 3], cv[3]);
            prod *= fmaf(sv[4], q[c0 + 4], cv[4]);
            if (w & 1)
                // permute so phase C reads hi[w + 8k] as one contiguous 16B
                hiT[pl][((lane & 7) << 2) | (lane >> 3)] = prod;
            else
                lo[pl][lane] = prod;
        }
        __syncthreads();

        // Phase C: codes n = tid + 256k.  n&31 = lane (conflict-free LDS),
        // n>>5 = w + 8k (broadcast LDS.128 -> two packed operands).
        #pragma unroll
        for (int pl = 0; pl < 16; pl++) {
            unsigned r = __float_as_uint(lo[pl][lane]);
            unsigned long long lv2;
            asm("mov.b64 %0, {%1, %1};" : "=l"(lv2) : "r"(r));
            ulonglong2 h = *(const ulonglong2*)&hiT[pl][w * 4];
            FMA2(a01, lv2, h.x);            // n = tid, tid+256
            FMA2(a23, lv2, h.y);            // n = tid+512, tid+768
        }
        __syncthreads();
    }

    // ---- Banked global accumulation (8 banks kill hot-spot contention) ----
    {
        float* bank = g_avg[blockIdx.x & (NBANK - 1)];
        unsigned x0, x1, x2, x3;
        asm("mov.b64 {%0, %1}, %2;" : "=r"(x0), "=r"(x1) : "l"(a01));
        asm("mov.b64 {%0, %1}, %2;" : "=r"(x2), "=r"(x3) : "l"(a23));
        atomicAdd(&bank[tid],       __uint_as_float(x0));
        atomicAdd(&bank[tid + 256], __uint_as_float(x1));
        atomicAdd(&bank[tid + 512], __uint_as_float(x2));
        atomicAdd(&bank[tid + 768], __uint_as_float(x3));
    }

    // ---- Last-block finalization (ticket) ----
    __threadfence();
    __syncthreads();
    if (tid == 0) s_ticket = atomicAdd(&g_count, 1u);
    __syncthreads();

    if (s_ticket == gridDim.x - 1) {        // uniform per block: syncs legal
        __threadfence();
        float ssum = 0.0f;
        #pragma unroll
        for (int k = 0; k < 4; k++) {
            int n = tid + 256 * k;
            float sa = 0.0f;
            #pragma unroll
            for (int b = 0; b < NBANK; b++) { sa += g_avg[b][n]; g_avg[b][n] = 0.0f; }
            float ap = sa * (1.0f / 65536.0f);
            ssum += -ap * logf(ap + 1e-5f);
        }
        #pragma unroll
        for (int o = 16; o; o >>= 1) ssum += __shfl_down_sync(0xffffffffu, ssum, o);
        if (lane == 0) s_red[w] = ssum;
        __syncthreads();
        if (tid < 32) {
            float v = (tid < 8) ? s_red[tid] : 0.0f;
            #pragma unroll
            for (int o = 4; o; o >>= 1) v += __shfl_down_sync(0xffffffffu, v, o);
            if (tid == 0) {
                float avg_entropy = v;                             // gamma = 1.0
                float pse = g_ent * (1.0f / 65536.0f);
                float cm  = 0.25f * g_commit * (1.0f / 655360.0f);
                out[OFF_LOSS] = cm + 0.1f * (pse - avg_entropy);
                out[OFF_PSE]  = pse;
                g_commit = 0.0f; g_ent = 0.0f; g_count = 0u;       // reset
            }
        }
    }
}

extern "C" void kernel_launch(void* const* d_in, const int* in_sizes, int n_in,
                              void* d_out, int out_size) {
    const float* z = (const float*)d_in[0];
    float* out = (float*)d_out;
    (void)in_sizes; (void)n_in; (void)out_size;
    k_fused<<<1024, 256>>>(z, out);
}

// round 14
// speedup vs baseline: 1.0881x; 1.0207x over previous
#include <cuda_runtime.h>
#include <math.h>

// z: (16, 10, 64, 64) f32.  B=16, C=10 bits, NPIX=65536, NELEM=655360.
// Output layout (f32, reference tuple order):
//   [0, 655360)        z_quantized (b,c,h,w)  = sign(z) in {-1,+1}
//   [655360]           loss
//   [655361]           per_sample_entropy
//   [655362, 720898)   min_encoding_indices (b,h,w) cast to float

#define OFF_LOSS  655360
#define OFF_PSE   655361
#define OFF_IDX   655362
#define NBANK     8

__device__ float    g_avg[NBANK][1024];
__device__ float    g_commit;
__device__ float    g_ent;
__device__ unsigned g_count;

// Packed f32x2 ops (sm_100+, PTX-only)
#define FMA2(d, a, b) \
    asm("fma.rn.f32x2 %0, %1, %2, %0;" : "+l"(d) : "l"(a), "l"(b))
#define FMA2G(d, a, b, c) \
    asm("fma.rn.f32x2 %0, %1, %2, %3;" : "=l"(d) : "l"(a), "l"(b), "l"(c))
#define MUL2(d, a, b) \
    asm("mul.rn.f32x2 %0, %1, %2;" : "=l"(d) : "l"(a), "l"(b))
#define PACK2(d, r) \
    asm("mov.b64 %0, {%1, %1};" : "=l"(d) : "r"(r))
#define UNPK2(x, y, d) \
    asm("mov.b64 {%0, %1}, %2;" : "=r"(x), "=r"(y) : "l"(d))

// One fused kernel, 1024 blocks x 64 pixels. The 1024-way softmax factorizes
// into 10 Bernoullis (q_c = sigmoid(400 z_c)):
//   p_n = lo[n&31] * hi[n>>5];  per_sample_entropy = sum of binary entropies.
// Everything in the mainloop is packed over pixel PAIRS as f32x2:
//   phase B: one thread builds a pixel-pair's 5-term subset product (FFMA2/MUL2)
//   phase C: 4 packed accumulators per thread (codes n = tid + 256k), no
//            barriers, lo via conflict-free LDS.128, hi via broadcast LDS.128.
__global__ void __launch_bounds__(256) k_fused(const float* __restrict__ z,
                                               float* __restrict__ out) {
    // qbp[pair][col][parity], col = c + (c>=5)  (gap keeps vectors aligned)
    __shared__ __align__(16) float qbp[32][12][2];   // 3 KB
    __shared__ __align__(16) float loT[32][68];      // lo[pixel] transposed, +4 pad
    __shared__ __align__(16) float hiP[32][32][2];   // [pair][perm(j)][parity]
    __shared__ float s_c[8], s_h[8], s_red[8];
    __shared__ unsigned s_ticket;

    int tid  = threadIdx.x;
    int lane = tid & 31;
    int w    = tid >> 5;
    int pix0 = blockIdx.x * 64;

    // ---- Load + elementwise pass (coalesced, c-major; 640 elems/block) ----
    float commit = 0.0f, H = 0.0f;
    #pragma unroll
    for (int k = 0; k < 3; k++) {
        int v = tid + k * 256;
        if (v < 640) {
            int c = v >> 6, p = v & 63;
            int pix = pix0 + p;
            int b = pix >> 12, hw = pix & 4095;
            int off = b * 40960 + c * 4096 + hw;
            float zv = z[off];
            bool s = (zv > 0.0f);
            float sg = s ? 1.0f : -1.0f;
            out[off] = sg;                  // z_quantized
            float d = sg - zv;
            commit += d * d;
            // binary entropy of q = sigmoid(400 zv): H2 = log(1+e) + t*e/(1+e)
            float t = 400.0f * fabsf(zv);
            float e = __expf(-t);
            float inv = 1.0f / (1.0f + e);
            H += __logf(1.0f + e) + t * e * inv;
            qbp[p >> 1][c + (c >= 5)][p & 1] = s ? inv : e * inv; // sigmoid
        }
    }
    #pragma unroll
    for (int o = 16; o; o >>= 1) {
        commit += __shfl_down_sync(0xffffffffu, commit, o);
        H      += __shfl_down_sync(0xffffffffu, H, o);
    }
    if (lane == 0) { s_c[w] = commit; s_h[w] = H; }
    __syncthreads();

    if (tid == 0) {                         // one pair of atomics per block
        float sc = 0.0f, sh = 0.0f;
        #pragma unroll
        for (int i = 0; i < 8; i++) { sc += s_c[i]; sh += s_h[i]; }
        atomicAdd(&g_commit, sc);
        atomicAdd(&g_ent, sh);
    }

    // ---- Index packing (q > 0.5  <=>  z > 0, incl. z==0 -> false) ----
    if (tid < 64) {
        int idx = 0;
        #pragma unroll
        for (int c = 0; c < 10; c++)
            idx |= ((int)(qbp[tid >> 1][c + (c >= 5)][tid & 1] > 0.5f)) << c;
        out[OFF_IDX + pix0 + tid] = (float)idx;
    }

    // ---- Phase B: subset products for all 64 pixels, pixel-pair packed ----
    // term_k = sv[k]*q + cv[k]; subset index i = lane for both halves.
    unsigned long long sv2[5], cv2[5];
    #pragma unroll
    for (int k = 0; k < 5; k++) {
        bool b = (lane >> k) & 1;
        PACK2(sv2[k], __float_as_uint(b ? 1.0f : -1.0f));
        PACK2(cv2[k], __float_as_uint(b ? 0.0f : 1.0f));
    }
    int half = w & 1;                        // 0: bits 0-4 (lo), 1: bits 5-9 (hi)
    int qoff = half * 12;                    // col 0.. or col 6.. (x2 floats)
    int perm = ((lane & 7) << 2) | (lane >> 3);

    #pragma unroll
    for (int jj = 0; jj < 8; jj++) {
        int pu = (w >> 1) + 4 * jj;          // pixel pair (2pu, 2pu+1)
        const float* qr = &qbp[pu][0][0] + qoff;
        ulonglong2 qa = *(const ulonglong2*)qr;         // cols +0,+1 (packed)
        ulonglong2 qb = *(const ulonglong2*)(qr + 4);   // cols +2,+3
        unsigned long long qc = *(const unsigned long long*)(qr + 8); // col +4
        unsigned long long t0, t1, t2, t3, t4, p2;
        FMA2G(t0, sv2[0], qa.x, cv2[0]);
        FMA2G(t1, sv2[1], qa.y, cv2[1]);
        FMA2G(t2, sv2[2], qb.x, cv2[2]);
        FMA2G(t3, sv2[3], qb.y, cv2[3]);
        FMA2G(t4, sv2[4], qc,   cv2[4]);
        MUL2(t0, t0, t1);
        MUL2(t2, t2, t3);
        MUL2(t0, t0, t4);
        MUL2(p2, t0, t2);
        if (half)
            *(unsigned long long*)&hiP[pu][perm][0] = p2;
        else
            *(unsigned long long*)&loT[lane][2 * pu] = p2;
    }
    __syncthreads();

    // ---- Phase C: barrier-free packed outer-product accumulation ----
    // acc[k] covers code n = tid + 256k: n&31 = lane, n>>5 = w + 8k = perm pos.
    unsigned long long a0 = 0ull, a1 = 0ull, a2 = 0ull, a3 = 0ull;
    const float* hbase = &hiP[0][w * 4][0];
    #pragma unroll
    for (int t = 0; t < 16; t++) {
        ulonglong2 L = *(const ulonglong2*)&loT[lane][4 * t];  // px 4t..4t+3
        const float* h0 = hbase + (2 * t) * 64;                // pair 2t
        ulonglong2 ha = *(const ulonglong2*)h0;
        ulonglong2 hb = *(const ulonglong2*)(h0 + 4);
        FMA2(a0, L.x, ha.x);
        FMA2(a1, L.x, ha.y);
        FMA2(a2, L.x, hb.x);
        FMA2(a3, L.x, hb.y);
        const float* h1 = h0 + 64;                             // pair 2t+1
        ulonglong2 hc = *(const ulonglong2*)h1;
        ulonglong2 hd = *(const ulonglong2*)(h1 + 4);
        FMA2(a0, L.y, hc.x);
        FMA2(a1, L.y, hc.y);
        FMA2(a2, L.y, hd.x);
        FMA2(a3, L.y, hd.y);
    }

    // ---- Banked global accumulation (8 banks kill hot-spot contention) ----
    {
        float* bank = g_avg[blockIdx.x & (NBANK - 1)];
        unsigned x, y;
        UNPK2(x, y, a0);
        atomicAdd(&bank[tid],       __uint_as_float(x) + __uint_as_float(y));
        UNPK2(x, y, a1);
        atomicAdd(&bank[tid + 256], __uint_as_float(x) + __uint_as_float(y));
        UNPK2(x, y, a2);
        atomicAdd(&bank[tid + 512], __uint_as_float(x) + __uint_as_float(y));
        UNPK2(x, y, a3);
        atomicAdd(&bank[tid + 768], __uint_as_float(x) + __uint_as_float(y));
    }

    // ---- Last-block finalization (ticket) ----
    __threadfence();
    __syncthreads();
    if (tid == 0) s_ticket = atomicAdd(&g_count, 1u);
    __syncthreads();

    if (s_ticket == gridDim.x - 1) {        // uniform per block: syncs legal
        __threadfence();
        float ssum = 0.0f;
        #pragma unroll
        for (int k = 0; k < 4; k++) {
            int n = tid + 256 * k;
            float sa = 0.0f;
            #pragma unroll
            for (int b = 0; b < NBANK; b++) { sa += g_avg[b][n]; g_avg[b][n] = 0.0f; }
            float ap = sa * (1.0f / 65536.0f);
            ssum += -ap * logf(ap + 1e-5f);
        }
        #pragma unroll
        for (int o = 16; o; o >>= 1) ssum += __shfl_down_sync(0xffffffffu, ssum, o);
        if (lane == 0) s_red[w] = ssum;
        __syncthreads();
        if (tid < 32) {
            float v = (tid < 8) ? s_red[tid] : 0.0f;
            #pragma unroll
            for (int o = 4; o; o >>= 1) v += __shfl_down_sync(0xffffffffu, v, o);
            if (tid == 0) {
                float avg_entropy = v;                             // gamma = 1.0
                float pse = g_ent * (1.0f / 65536.0f);
                float cm  = 0.25f * g_commit * (1.0f / 655360.0f);
                out[OFF_LOSS] = cm + 0.1f * (pse - avg_entropy);
                out[OFF_PSE]  = pse;
                g_commit = 0.0f; g_ent = 0.0f; g_count = 0u;       // reset
            }
        }
    }
}

extern "C" void kernel_launch(void* const* d_in, const int* in_sizes, int n_in,
                              void* d_out, int out_size) {
    const float* z = (const float*)d_in[0];
    float* out = (float*)d_out;
    (void)in_sizes; (void)n_in; (void)out_size;
    k_fused<<<1024, 256>>>(z, out);
}

// round 17
// speedup vs baseline: 1.5479x; 1.4226x over previous
#include <cuda_runtime.h>
#include <math.h>

// z: (16, 10, 64, 64) f32.  B=16, C=10 bits, NPIX=65536, NELEM=655360.
// Output layout (f32, reference tuple order):
//   [0, 655360)        z_quantized (b,c,h,w)  = sign(z) in {-1,+1}
//   [655360]           loss
//   [655361]           per_sample_entropy
//   [655362, 720898)   min_encoding_indices (b,h,w) cast to float

#define OFF_LOSS  655360
#define OFF_PSE   655361
#define OFF_IDX   655362
#define NBANK     8
#define THETA     1e-3f

__device__ float    g_avg[NBANK][1024];
__device__ float    g_commit;
__device__ float    g_ent;
__device__ unsigned g_count;

// One fused kernel, 512 blocks x 128 threads, one pixel per thread.
//
// With temperature 0.01 the 1024-way softmax is a product of 10 Bernoullis
// q_c = sigmoid(400 z_c).  Let e_c = exp(-400|z_c|), inv_c = 1/(1+e_c),
// P0 = prod_c inv_c, idx = sign code.  Then EXACTLY:
//     p_n = P0 * prod_{c in n XOR idx} e_c
// i.e. a product measure centered at idx with per-bit flip weight e_c.
// Bits with e_c <= THETA contribute < 2e-6 expected mass each and are
// truncated; flagged bits (e_c > THETA, ~1.4% per channel) are handled
// exactly: singles always (unrolled), all >=2-flip subsets of the flagged
// set via a compact enumeration loop (rare: ~0.9% of pixels).
// avg_probs becomes a sparse histogram (~1.3 adds/pixel) instead of a dense
// 65536x1024 evaluation.  per_sample_entropy = sum of binary entropies
// (exact); commitment and indices exact.
__global__ void __launch_bounds__(128) k_fused(const float* __restrict__ z,
                                               float* __restrict__ out) {
    __shared__ float hist[1024];
    __shared__ float s_c[4], s_h[4], s_red[4];
    __shared__ unsigned s_ticket;

    int tid  = threadIdx.x;
    int lane = tid & 31;
    int w    = tid >> 5;
    int pix  = blockIdx.x * 128 + tid;
    int b = pix >> 12, hw = pix & 4095;
    const float* zp = z + b * 40960 + hw;
    float* op = out + b * 40960 + hw;

    #pragma unroll
    for (int k = 0; k < 8; k++) hist[tid + 128 * k] = 0.0f;
    __syncthreads();

    // ---- Per-pixel channel loop (10 coalesced LDG, MLP=10) ----
    float e[10];
    float commit = 0.0f, H = 0.0f, P0 = 1.0f;
    int idx = 0;
    unsigned F = 0;
    #pragma unroll
    for (int c = 0; c < 10; c++) {
        float zv = zp[c * 4096];
        bool s = (zv > 0.0f);
        float sg = s ? 1.0f : -1.0f;
        op[c * 4096] = sg;                  // z_quantized
        float d = sg - zv;
        commit += d * d;
        float t = 400.0f * fabsf(zv);
        float ec = __expf(-t);
        e[c] = ec;
        float inv = 1.0f / (1.0f + ec);
        // binary entropy of q: H2 = log(1+e) + t*e/(1+e)
        H += __logf(1.0f + ec) + t * ec * inv;
        P0 *= inv;
        idx |= ((int)s) << c;
        F |= ((unsigned)(ec > THETA)) << c;
    }
    out[OFF_IDX + pix] = (float)idx;

    // ---- Sparse probability mass -> block histogram ----
    atomicAdd(&hist[idx], P0);                           // 0-flip (dominant)
    if (F) {                                             // 1-flip terms
        #pragma unroll
        for (int c = 0; c < 10; c++)
            if ((F >> c) & 1)
                atomicAdd(&hist[idx ^ (1 << c)], P0 * e[c]);
    }
    int f = __popc(F);
    if (__any_sync(0xffffffffu, f >= 2)) {   // all >=2-flip subsets, exact
        if (f >= 2) {
            float fe[10]; int fb[10]; int cnt = 0;
            #pragma unroll
            for (int c = 0; c < 10; c++)
                if ((F >> c) & 1) { fe[cnt] = e[c]; fb[cnt] = 1 << c; cnt++; }
            int lim = 1 << cnt;
            for (int s = 3; s < lim; s++) {
                if (__popc(s) < 2) continue;
                float wgt = P0; int m = idx;
                for (int k = 0; k < cnt; k++)
                    if ((s >> k) & 1) { wgt *= fe[k]; m ^= fb[k]; }
                atomicAdd(&hist[m], wgt);
            }
        }
    }

    // ---- Reduce commit / per-sample entropy ----
    #pragma unroll
    for (int o = 16; o; o >>= 1) {
        commit += __shfl_down_sync(0xffffffffu, commit, o);
        H      += __shfl_down_sync(0xffffffffu, H, o);
    }
    if (lane == 0) { s_c[w] = commit; s_h[w] = H; }
    __syncthreads();
    if (tid == 0) {
        atomicAdd(&g_commit, s_c[0] + s_c[1] + s_c[2] + s_c[3]);
        atomicAdd(&g_ent,    s_h[0] + s_h[1] + s_h[2] + s_h[3]);
    }

    // ---- Sparse flush of block histogram to banked global ----
    {
        float* bank = g_avg[blockIdx.x & (NBANK - 1)];
        #pragma unroll
        for (int k = 0; k < 8; k++) {
            int n = tid + 128 * k;
            float v = hist[n];
            if (v != 0.0f) atomicAdd(&bank[n], v);   // most entries are zero
        }
    }

    // ---- Last-block finalization (ticket) ----
    __threadfence();
    __syncthreads();
    if (tid == 0) s_ticket = atomicAdd(&g_count, 1u);
    __syncthreads();

    if (s_ticket == gridDim.x - 1) {        // uniform per block: syncs legal
        __threadfence();
        float ssum = 0.0f;
        #pragma unroll
        for (int k = 0; k < 8; k++) {
            int n = tid + 128 * k;
            float sa = 0.0f;
            #pragma unroll
            for (int bk = 0; bk < NBANK; bk++) { sa += g_avg[bk][n]; g_avg[bk][n] = 0.0f; }
            float ap = sa * (1.0f / 65536.0f);
            ssum += -ap * logf(ap + 1e-5f);
        }
        #pragma unroll
        for (int o = 16; o; o >>= 1) ssum += __shfl_down_sync(0xffffffffu, ssum, o);
        if (lane == 0) s_red[w] = ssum;
        __syncthreads();
        if (tid < 32) {
            float v = (tid < 4) ? s_red[tid] : 0.0f;
            #pragma unroll
            for (int o = 2; o; o >>= 1) v += __shfl_down_sync(0xffffffffu, v, o);
            if (tid == 0) {
                float avg_entropy = v;                             // gamma = 1.0
                float pse = g_ent * (1.0f / 65536.0f);
                float cm  = 0.25f * g_commit * (1.0f / 655360.0f);
                out[OFF_LOSS] = cm + 0.1f * (pse - avg_entropy);
                out[OFF_PSE]  = pse;
                g_commit = 0.0f; g_ent = 0.0f; g_count = 0u;       // reset
            }
        }
    }
}

extern "C" void kernel_launch(void* const* d_in, const int* in_sizes, int n_in,
                              void* d_out, int out_size) {
    const float* z = (const float*)d_in[0];
    float* out = (float*)d_out;
    (void)in_sizes; (void)n_in; (void)out_size;
    k_fused<<<512, 128>>>(z, out);
}